// round 12
// baseline (speedup 1.0000x reference)
#include <cuda_runtime.h>

// HermiteFuncs: x[B,n,N] -> psi[B,n,R,N], R=6
//   t  = tanh(x) * sqrt(2R+1)
//   g  = exp(-t^2/2)
//   psi0 = c*g, psi1 = sqrt(2)*c*t*g,  c = pi^(-1/4)
//   psi_k = sqrt(2/k)*t*psi_{k-1} - sqrt((k-1)/k)*psi_{k-2}
//
// Pure HBM-bound elementwise op (32 MB in, 201 MB out). One thread per
// float4; 6 coalesced float4 stores per thread.

#define R_FUNCS 6
#define SCALE   3.6055512754639896f   /* sqrt(13) */
#define C_PI4   0.7511255444649425f   /* pi^-0.25 */
#define SQRT2   1.4142135623730951f

// recurrence coefficients a_k = sqrt(2/k), b_k = sqrt((k-1)/k), k = 2..5
__device__ __constant__ float2 RECUR[4] = {
    {1.0000000000000000f, 0.7071067811865476f},  // k=2
    {0.8164965809277260f, 0.8164965809277260f},  // k=3
    {0.7071067811865476f, 0.8660254037844386f},  // k=4
    {0.6324555320336759f, 0.8944271909999159f},  // k=5
};

__device__ __forceinline__ void hermite6(float xin, float out[R_FUNCS]) {
    float t = tanhf(xin) * SCALE;
    float g = __expf(-0.5f * t * t);
    float p0 = C_PI4 * g;
    float p1 = SQRT2 * C_PI4 * t * g;
    out[0] = p0;
    out[1] = p1;
#pragma unroll
    for (int k = 2; k < R_FUNCS; ++k) {
        float2 ab = RECUR[k - 2];
        float pk = ab.x * t * p1 - ab.y * p0;
        out[k] = pk;
        p0 = p1;
        p1 = pk;
    }
}

__global__ void __launch_bounds__(256)
hermite_kernel(const float4* __restrict__ x, float4* __restrict__ out,
               int total_vec) {
    int idx = blockIdx.x * blockDim.x + threadIdx.x;
    if (idx >= total_vec) return;

    float4 v = x[idx];                 // one coalesced 128-bit load

    int row = idx >> 10;               // 4096 floats = 1024 vec4 per row
    int col = idx & 1023;
    long long base = (long long)row * (R_FUNCS * 1024) + col;

    float px[R_FUNCS], py[R_FUNCS], pz[R_FUNCS], pw[R_FUNCS];
    hermite6(v.x, px);
    hermite6(v.y, py);
    hermite6(v.z, pz);
    hermite6(v.w, pw);

#pragma unroll
    for (int r = 0; r < R_FUNCS; ++r) {
        float4 o;
        o.x = px[r]; o.y = py[r]; o.z = pz[r]; o.w = pw[r];
        out[base + (long long)r * 1024] = o;  // coalesced across warp
    }
}

extern "C" void kernel_launch(void* const* d_in, const int* in_sizes, int n_in,
                              void* d_out, int out_size) {
    const float4* x = (const float4*)d_in[0];
    float4* out = (float4*)d_out;
    int total_vec = in_sizes[0] / 4;          // 2,097,152 for [32,64,4096]
    int threads = 256;
    int blocks = (total_vec + threads - 1) / threads;
    hermite_kernel<<<blocks, threads>>>(x, out, total_vec);
}